// round 1
// baseline (speedup 1.0000x reference)
#include <cuda_runtime.h>

#define T_STEPS 512
#define BATCH   256
#define INDIM   8
#define HID     512
#define OUTD    5
#define NCTA    96
#define NL0     32
#define THREADS 256
#define WST     516            // padded SMEM row stride (floats): conflict-free B loads
#define NPHASE  (T_STEPS + 1)  // 513 phases (pipelined: phase p -> h0[p], h1[p-1])

// Persistent state (device globals: no allocations allowed)
__device__ float    g_h0[2][BATCH * HID];
__device__ float    g_h1[2][BATCH * HID];
__device__ unsigned g_bar[NPHASE];

__device__ __forceinline__ float to_tf32(float x) {
    float r; asm("cvt.rna.tf32.f32 %0, %1;" : "=f"(r) : "f"(x)); return r;
}
__device__ __forceinline__ float sigmoidf_(float x) {
    return 1.f / (1.f + __expf(-x));
}
__device__ __forceinline__ float tanhf_(float x) {
    float e = __expf(2.f * x);          // overflow -> inf -> returns 1.0 correctly
    return 1.f - 2.f / (e + 1.f);
}
__device__ __forceinline__ void mma_tf32(float* c, const unsigned* a, unsigned b0, unsigned b1) {
    asm volatile(
        "mma.sync.aligned.m16n8k8.row.col.f32.tf32.tf32.f32 "
        "{%0,%1,%2,%3}, {%4,%5,%6,%7}, {%8,%9}, {%0,%1,%2,%3};\n"
        : "+f"(c[0]), "+f"(c[1]), "+f"(c[2]), "+f"(c[3])
        : "r"(a[0]), "r"(a[1]), "r"(a[2]), "r"(a[3]), "r"(b0), "r"(b1));
}
__device__ __forceinline__ float ldcg(const float* p) { return __ldcg(p); }

// Device-wide sense-free barrier: one counter per phase, reset each launch.
__device__ __forceinline__ void grid_barrier(int p) {
    __syncthreads();
    if (threadIdx.x == 0) {
        unsigned* c = &g_bar[p];
        asm volatile("red.release.gpu.global.add.u32 [%0], %1;" :: "l"(c), "r"(1u) : "memory");
        unsigned v;
        do {
            asm volatile("ld.acquire.gpu.global.u32 %0, [%1];" : "=r"(v) : "l"(c) : "memory");
        } while (v < NCTA);
    }
    __syncthreads();
}

__global__ void reset_kernel() {
    int tid = blockIdx.x * blockDim.x + threadIdx.x;
    int stride = gridDim.x * blockDim.x;
    for (int i = tid; i < BATCH * HID; i += stride) { g_h0[1][i] = 0.f; g_h1[1][i] = 0.f; }
    if (tid < NPHASE) g_bar[tid] = 0u;
}

extern __shared__ float smem[];

__global__ void __launch_bounds__(THREADS, 1) gru_persistent(
    const float* __restrict__ x,
    const float* __restrict__ Wih0, const float* __restrict__ Whh0,
    const float* __restrict__ bih0, const float* __restrict__ bhh0,
    const float* __restrict__ Wih1, const float* __restrict__ Whh1,
    const float* __restrict__ bih1, const float* __restrict__ bhh1,
    const float* __restrict__ Wout, const float* __restrict__ bout,
    float* __restrict__ out)
{
    float* Wsm   = smem;                  // 48 x WST  (tf32 weight tile)
    float* xsm   = Wsm + 48 * WST;        // 256 x 8   (x_t tile, layer0 only)
    float* wihsm = xsm + BATCH * INDIM;   // 48 x 8    (W_ih0 slice, fp32)
    float* bihsm = wihsm + 48 * INDIM;    // 48
    float* bhhsm = bihsm + 48;            // 48

    const int tid  = threadIdx.x;
    const int cta  = blockIdx.x;
    const bool l0  = (cta < NL0);
    const int lane = tid & 31;
    const int warp = tid >> 5;
    const int gid  = lane >> 2;
    const int q    = lane & 3;
    const int rowbase = warp * 32;

    // ---- stage weights ONCE (persistent kernel) ----
    if (l0) {
        const int U0 = cta * 16;
        for (int i = tid; i < 48 * HID; i += THREADS) {
            int j = i >> 9, k = i & (HID - 1);
            int g = (j < 16) ? (U0 + j) : (j < 32) ? (512 + U0 + j - 16) : (1024 + U0 + j - 32);
            Wsm[j * WST + k] = to_tf32(Whh0[g * HID + k]);
        }
        for (int i = tid; i < 48 * INDIM; i += THREADS) {
            int j = i >> 3, k = i & 7;
            int g = (j < 16) ? (U0 + j) : (j < 32) ? (512 + U0 + j - 16) : (1024 + U0 + j - 32);
            wihsm[j * INDIM + k] = Wih0[g * INDIM + k];
        }
        if (tid < 48) {
            int j = tid;
            int g = (j < 16) ? (U0 + j) : (j < 32) ? (512 + U0 + j - 16) : (1024 + U0 + j - 32);
            bihsm[j] = bih0[g];
            bhhsm[j] = bhh0[g];
        }
    } else {
        const int U1 = (cta - NL0) * 8;
        for (int i = tid; i < 48 * HID; i += THREADS) {
            int j = i >> 9, k = i & (HID - 1);
            int jj = (j < 24) ? j : (j - 24);
            int g = (jj < 8) ? (U1 + jj) : (jj < 16) ? (512 + U1 + jj - 8) : (1024 + U1 + jj - 16);
            const float* W = (j < 24) ? Wih1 : Whh1;
            Wsm[j * WST + k] = to_tf32(W[g * HID + k]);
        }
        if (tid < 24) {
            int jj = tid;
            int g = (jj < 8) ? (U1 + jj) : (jj < 16) ? (512 + U1 + jj - 8) : (1024 + U1 + jj - 16);
            bihsm[jj] = bih1[g];
            bhhsm[jj] = bhh1[g];
        }
    }
    __syncthreads();

    for (int p = 0; p < NPHASE; ++p) {
        if (l0) {
            if (p < T_STEPS) {
                // stage x_t (2048 floats)
                const float4* xp = (const float4*)(x + (size_t)p * BATCH * INDIM);
                float4* xd = (float4*)xsm;
                xd[tid] = xp[tid];
                xd[tid + THREADS] = xp[tid + THREADS];
                __syncthreads();

                const float* A  = g_h0[(unsigned)(p - 1) & 1u];  // h0[p-1]
                float* Hn = g_h0[p & 1];                          // h0[p]
                const int U0 = cta * 16;

                float acc[2][6][4];
                #pragma unroll
                for (int mt = 0; mt < 2; ++mt)
                    #pragma unroll
                    for (int nt = 0; nt < 6; ++nt)
                        #pragma unroll
                        for (int e = 0; e < 4; ++e) acc[mt][nt][e] = 0.f;

                #pragma unroll 4
                for (int kc = 0; kc < HID / 8; ++kc) {
                    const int k = kc * 8 + q;
                    unsigned a[2][4];
                    #pragma unroll
                    for (int mt = 0; mt < 2; ++mt) {
                        const int rb = (rowbase + mt * 16 + gid) * HID;
                        a[mt][0] = __float_as_uint(ldcg(A + rb + k));
                        a[mt][1] = __float_as_uint(ldcg(A + rb + 8 * HID + k));
                        a[mt][2] = __float_as_uint(ldcg(A + rb + k + 4));
                        a[mt][3] = __float_as_uint(ldcg(A + rb + 8 * HID + k + 4));
                    }
                    #pragma unroll
                    for (int nt = 0; nt < 6; ++nt) {
                        unsigned b0 = __float_as_uint(Wsm[(nt * 8 + gid) * WST + k]);
                        unsigned b1 = __float_as_uint(Wsm[(nt * 8 + gid) * WST + k + 4]);
                        mma_tf32(acc[0][nt], a[0], b0, b1);
                        mma_tf32(acc[1][nt], a[1], b0, b1);
                    }
                }

                // epilogue: GRU cell, thread-local (cols 0..15 r | 16..31 z | 32..47 n)
                #pragma unroll
                for (int mt = 0; mt < 2; ++mt)
                #pragma unroll
                for (int hh = 0; hh < 2; ++hh) {
                    const int row = rowbase + mt * 16 + gid + hh * 8;
                    const float* xrow = xsm + row * INDIM;
                    #pragma unroll
                    for (int g2 = 0; g2 < 2; ++g2)
                    #pragma unroll
                    for (int e = 0; e < 2; ++e) {
                        const int u = g2 * 8 + q * 2 + e;
                        const int cr = hh * 2 + e;
                        float hr = acc[mt][0 + g2][cr];
                        float hz = acc[mt][2 + g2][cr];
                        float hn = acc[mt][4 + g2][cr];
                        float xr = bihsm[u], xz = bihsm[16 + u], xn = bihsm[32 + u];
                        #pragma unroll
                        for (int k = 0; k < INDIM; ++k) {
                            float xv = xrow[k];
                            xr += xv * wihsm[u * INDIM + k];
                            xz += xv * wihsm[(16 + u) * INDIM + k];
                            xn += xv * wihsm[(32 + u) * INDIM + k];
                        }
                        float rg = sigmoidf_(xr + hr + bhhsm[u]);
                        float zg = sigmoidf_(xz + hz + bhhsm[16 + u]);
                        float ng = tanhf_(xn + rg * (hn + bhhsm[32 + u]));
                        float hp = ldcg(A + row * HID + U0 + u);
                        __stcg(Hn + row * HID + U0 + u, to_tf32((1.f - zg) * ng + zg * hp));
                    }
                }
            }
        } else {
            if (p >= 1) {
                const float* A0 = g_h0[(unsigned)(p - 1) & 1u];  // h0[p-1]
                const float* A1 = g_h1[(unsigned)p & 1u];        // h1[p-2]
                float* Hn = g_h1[(unsigned)(p - 1) & 1u];        // h1[p-1]
                const int U1 = (cta - NL0) * 8;

                float acc[2][6][4];
                #pragma unroll
                for (int mt = 0; mt < 2; ++mt)
                    #pragma unroll
                    for (int nt = 0; nt < 6; ++nt)
                        #pragma unroll
                        for (int e = 0; e < 4; ++e) acc[mt][nt][e] = 0.f;

                #pragma unroll 4
                for (int kc = 0; kc < HID / 8; ++kc) {
                    const int k = kc * 8 + q;
                    unsigned a0[2][4], a1[2][4];
                    #pragma unroll
                    for (int mt = 0; mt < 2; ++mt) {
                        const int rb = (rowbase + mt * 16 + gid) * HID;
                        a0[mt][0] = __float_as_uint(ldcg(A0 + rb + k));
                        a0[mt][1] = __float_as_uint(ldcg(A0 + rb + 8 * HID + k));
                        a0[mt][2] = __float_as_uint(ldcg(A0 + rb + k + 4));
                        a0[mt][3] = __float_as_uint(ldcg(A0 + rb + 8 * HID + k + 4));
                        a1[mt][0] = __float_as_uint(ldcg(A1 + rb + k));
                        a1[mt][1] = __float_as_uint(ldcg(A1 + rb + 8 * HID + k));
                        a1[mt][2] = __float_as_uint(ldcg(A1 + rb + k + 4));
                        a1[mt][3] = __float_as_uint(ldcg(A1 + rb + 8 * HID + k + 4));
                    }
                    #pragma unroll
                    for (int nt = 0; nt < 6; ++nt) {
                        unsigned b0 = __float_as_uint(Wsm[(nt * 8 + gid) * WST + k]);
                        unsigned b1 = __float_as_uint(Wsm[(nt * 8 + gid) * WST + k + 4]);
                        if (nt < 3) {
                            mma_tf32(acc[0][nt], a0[0], b0, b1);
                            mma_tf32(acc[1][nt], a0[1], b0, b1);
                        } else {
                            mma_tf32(acc[0][nt], a1[0], b0, b1);
                            mma_tf32(acc[1][nt], a1[1], b0, b1);
                        }
                    }
                }

                // epilogue: cols 0..7 gi_r | 8..15 gi_z | 16..23 gi_n | 24..31 gh_r | 32..39 gh_z | 40..47 gh_n
                #pragma unroll
                for (int mt = 0; mt < 2; ++mt)
                #pragma unroll
                for (int hh = 0; hh < 2; ++hh) {
                    const int row = rowbase + mt * 16 + gid + hh * 8;
                    #pragma unroll
                    for (int e = 0; e < 2; ++e) {
                        const int u = q * 2 + e;
                        const int cr = hh * 2 + e;
                        float ir  = acc[mt][0][cr];
                        float iz  = acc[mt][1][cr];
                        float inn = acc[mt][2][cr];
                        float hr  = acc[mt][3][cr];
                        float hz  = acc[mt][4][cr];
                        float hn  = acc[mt][5][cr];
                        float rg = sigmoidf_(ir + bihsm[u] + hr + bhhsm[u]);
                        float zg = sigmoidf_(iz + bihsm[8 + u] + hz + bhhsm[8 + u]);
                        float ng = tanhf_(inn + bihsm[16 + u] + rg * (hn + bhhsm[16 + u]));
                        float hp = ldcg(A1 + row * HID + U1 + u);
                        __stcg(Hn + row * HID + U1 + u, to_tf32((1.f - zg) * ng + zg * hp));
                    }
                }
            }
        }
        grid_barrier(p);
    }

    // linear head: out = h1[T-1] @ Wout^T + bout   (CTA 0, one row per thread)
    if (cta == 0) {
        const float* hrow = g_h1[(T_STEPS - 1) & 1] + (size_t)tid * HID;
        float acc[OUTD];
        #pragma unroll
        for (int o = 0; o < OUTD; ++o) acc[o] = bout[o];
        #pragma unroll 4
        for (int k = 0; k < HID; ++k) {
            float hv = ldcg(hrow + k);
            #pragma unroll
            for (int o = 0; o < OUTD; ++o) acc[o] += hv * __ldg(&Wout[o * HID + k]);
        }
        #pragma unroll
        for (int o = 0; o < OUTD; ++o) out[tid * OUTD + o] = acc[o];
    }
}

extern "C" void kernel_launch(void* const* d_in, const int* in_sizes, int n_in,
                              void* d_out, int out_size) {
    const float* x     = (const float*)d_in[0];
    const float* Wih0  = (const float*)d_in[1];
    const float* Whh0  = (const float*)d_in[2];
    const float* bih0  = (const float*)d_in[3];
    const float* bhh0  = (const float*)d_in[4];
    const float* Wih1  = (const float*)d_in[5];
    const float* Whh1  = (const float*)d_in[6];
    const float* bih1  = (const float*)d_in[7];
    const float* bhh1  = (const float*)d_in[8];
    const float* Wout  = (const float*)d_in[9];
    const float* bout  = (const float*)d_in[10];
    float* out = (float*)d_out;

    const int smem_bytes = (48 * WST + BATCH * INDIM + 48 * INDIM + 96) * sizeof(float);
    cudaFuncSetAttribute(gru_persistent, cudaFuncAttributeMaxDynamicSharedMemorySize, smem_bytes);

    reset_kernel<<<128, 256>>>();
    gru_persistent<<<NCTA, THREADS, smem_bytes>>>(
        x, Wih0, Whh0, bih0, bhh0, Wih1, Whh1, bih1, bhh1, Wout, bout, out);
}